// round 11
// baseline (speedup 1.0000x reference)
#include <cuda_runtime.h>
#include <cuda_fp16.h>
#include <math.h>
#include <stdint.h>

// Net_R1L: single-layer ReLU RNN, B=4096, T=2048, NIN=3, NHID=5, NOUT=1
//
// Round 11 = R10 (fp16 consumer, 55.8us, rel_err 1.1e-4) + LDS latency fix.
// R10 residual: ~49 cyc/step vs 30-cyc HFMA2 issue floor. ~15 cyc = exposed
// LDS latency (u loaded at top of each step, consumed immediately; ptxas did
// not pipeline the loads). Fixes:
//  1. u packed as ONE 16B word {u01,u23,u4x,pad}: single LDS.128/step
//     (and a single STS.128/step for producers). Lane*16B -> conflict-free.
//  2. Explicit one-step rolling prefetch: load u[s+1] before computing s.
//     29-cyc LDS latency hides under the ~30-cyc step; one exposed LDS per
//     32-step tile at the barrier edge.
// Everything else identical to R10 (producers, 3-deep cp.async x ring,
// split named barriers, producer bar.sync 1,96).

#define TT 2048
#define NIN3 3
#define NH 5
#define TSU 32                  // steps per u tile
#define NTU (TT / TSU)          // 64
#define XSTRIDE 100             // floats per row per x tile (96 data + 4 pad)
#define XB 3                    // x ring depth

// ---- dynamic smem layout (bytes) ----
#define OFF_U   0
#define SZ_U    (2 * TSU * 32 * 16)          // 32768: {u01,u23,u4x,pad}
#define OFF_XS  (OFF_U + SZ_U)
#define SZ_XS   (XB * 32 * XSTRIDE * 4)      // 38400
#define SMEM_TOTAL (OFF_XS + SZ_XS)          // 71168

static __device__ __forceinline__ uint32_t h2u(__half2 h) {
    return *reinterpret_cast<uint32_t*>(&h);
}
static __device__ __forceinline__ __half2 u2h(uint32_t u) {
    return *reinterpret_cast<__half2*>(&u);
}

static __device__ __forceinline__ void cp16(uint32_t saddr, const void* gaddr) {
    asm volatile("cp.async.cg.shared.global [%0], [%1], 16;"
                 :: "r"(saddr), "l"(gaddr) : "memory");
}
static __device__ __forceinline__ void cp_commit() {
    asm volatile("cp.async.commit_group;" ::: "memory");
}
static __device__ __forceinline__ void cp_wait1() {
    asm volatile("cp.async.wait_group 1;" ::: "memory");
}
static __device__ __forceinline__ void producer_bar() {   // 3 warps, id 1
    asm volatile("bar.sync 1, 96;" ::: "memory");
}
static __device__ __forceinline__ void bar_sync128(int id) {
    asm volatile("bar.sync %0, 128;" :: "r"(id) : "memory");
}
static __device__ __forceinline__ void bar_arrive128(int id) {
    asm volatile("bar.arrive %0, 128;" :: "r"(id) : "memory");
}

__global__ void __launch_bounds__(128, 1) rnn_relu_kernel(
    const float* __restrict__ state,   // [B, T, 3]
    const float* __restrict__ W_ih,    // [5, 3]
    const float* __restrict__ W_hh,    // [5, 5]
    const float* __restrict__ b_ih,    // [5]
    const float* __restrict__ b_hh,    // [5]
    const float* __restrict__ W_out,   // [1, 5]
    const float* __restrict__ b_out,   // [1]
    float* __restrict__ out,           // [B, 1]
    int B)
{
    extern __shared__ char dsm[];
    const uint32_t smem_u32 = (uint32_t)__cvta_generic_to_shared(dsm);
    float* const xsp = (float*)(dsm + OFF_XS);

    const int tid   = threadIdx.x;
    const int wid   = tid >> 5;
    const int lane  = tid & 31;
    const int bbase = blockIdx.x * 32;

    if (wid == 0) {
        // ================= CONSUMER WARP: fp16 serial recurrence ============
        __half2 w01[NH], w23[NH], w4x[NH];
#pragma unroll
        for (int k = 0; k < NH; k++) {
            w01[k] = __floats2half2_rn(__ldg(&W_hh[0 * NH + k]),
                                       __ldg(&W_hh[1 * NH + k]));
            w23[k] = __floats2half2_rn(__ldg(&W_hh[2 * NH + k]),
                                       __ldg(&W_hh[3 * NH + k]));
            w4x[k] = __floats2half2_rn(__ldg(&W_hh[4 * NH + k]), 0.0f);
        }
        const __half2 z2 = __float2half2_rn(0.0f);

        __half2 h01 = z2, h23 = z2, h4x = z2;

        const uint32_t ubase = smem_u32 + OFF_U + (uint32_t)lane * 16;

        for (int t = 0; t < NTU; ++t) {
            const int par = t & 1;
            bar_sync128(2 + par);            // wait "ready": u[t] published

            const uint32_t tb = ubase + (uint32_t)par * (TSU * 32 * 16);

            // Rolling prefetch: load u[s+1] before computing step s.
            uint32_t na, nb, nc, nd;
            asm("ld.shared.v4.u32 {%0, %1, %2, %3}, [%4];"
                : "=r"(na), "=r"(nb), "=r"(nc), "=r"(nd) : "r"(tb));
#pragma unroll
            for (int s = 0; s < TSU; ++s) {
                const __half2 u01 = u2h(na);
                const __half2 u23 = u2h(nb);
                const __half2 u4x = u2h(nc);
                if (s + 1 < TSU) {
                    asm("ld.shared.v4.u32 {%0, %1, %2, %3}, [%4];"
                        : "=r"(na), "=r"(nb), "=r"(nc), "=r"(nd)
                        : "r"(tb + (s + 1) * (32 * 16)));
                }

                const __half2 s0 = __low2half2(h01);
                const __half2 s1 = __high2half2(h01);
                const __half2 s2 = __low2half2(h23);
                const __half2 s3 = __high2half2(h23);
                const __half2 s4 = __low2half2(h4x);

                __half2 a01 = __hfma2(s0, w01[0], u01);
                __half2 a23 = __hfma2(s0, w23[0], u23);
                __half2 a4  = __hfma2(s0, w4x[0], u4x);
                a01 = __hfma2(s1, w01[1], a01);
                a23 = __hfma2(s1, w23[1], a23);
                a4  = __hfma2(s1, w4x[1], a4);
                a01 = __hfma2(s2, w01[2], a01);
                a23 = __hfma2(s2, w23[2], a23);
                a4  = __hfma2(s2, w4x[2], a4);
                a01 = __hfma2(s3, w01[3], a01);
                a23 = __hfma2(s3, w23[3], a23);
                a4  = __hfma2(s3, w4x[3], a4);
                a01 = __hfma2(s4, w01[4], a01);
                a23 = __hfma2(s4, w23[4], a23);
                a4  = __hfma2(s4, w4x[4], a4);

                h01 = __hmax2(a01, z2);
                h23 = __hmax2(a23, z2);
                h4x = __hmax2(a4, z2);
            }
            bar_arrive128(4 + par);          // signal "free": u[t] consumed
        }

        // Readout in fp32: tanh(W_out @ h_T + b_out)
        float o = __ldg(&b_out[0]);
        o = fmaf(__low2float(h01),  __ldg(&W_out[0]), o);
        o = fmaf(__high2float(h01), __ldg(&W_out[1]), o);
        o = fmaf(__low2float(h23),  __ldg(&W_out[2]), o);
        o = fmaf(__high2float(h23), __ldg(&W_out[3]), o);
        o = fmaf(__low2float(h4x),  __ldg(&W_out[4]), o);
        out[bbase + lane] = tanhf(o);
    } else {
        // ================= PRODUCER WARPS: x staging + fp32 x-projection ====
        float wih[NH][NIN3], c[NH];
#pragma unroll
        for (int j = 0; j < NH; j++) {
#pragma unroll
            for (int i = 0; i < NIN3; i++) wih[j][i] = __ldg(&W_ih[j * NIN3 + i]);
            c[j] = __ldg(&b_ih[j]) + __ldg(&b_hh[j]);
        }

        // cp.async mapping: wtid in [0,96): row = wtid/3, seg = wtid%3.
        // Each thread copies 32 consecutive floats (8x cp16) of its row's
        // 96-float tile slice.
        const int wtid = tid - 32;
        const int crow = wtid / 3;
        const int cseg = wtid % 3;
        const float* grow = state + (size_t)(bbase + crow) * (TT * NIN3) + cseg * 32;
        const uint32_t s_x = smem_u32 + OFF_XS
                           + (uint32_t)(crow * XSTRIDE + cseg * 32) * 4;
        const uint32_t xbufsz = (uint32_t)(32 * XSTRIDE * 4);

        // Per-warp step range within a 32-step tile (11/11/10).
        const int s_begin = (wid == 1) ? 0 : (wid == 2) ? 11 : 22;
        const int s_end   = (wid == 1) ? 11 : (wid == 2) ? 22 : 32;
        const int prow    = lane;

        auto issue_x = [&](int tile, int buf) {
            const float* g = grow + (size_t)tile * (TSU * NIN3);
            const uint32_t s0 = s_x + (uint32_t)buf * xbufsz;
#pragma unroll
            for (int k = 0; k < 8; k++) cp16(s0 + k * 16, g + k * 4);
            cp_commit();
        };

        auto compute_u = [&](int xbuf, int ubuf) {
            const float* xr = xsp + (size_t)xbuf * (32 * XSTRIDE)
                                  + (size_t)prow * XSTRIDE;
            const uint32_t ub = smem_u32 + OFF_U
                              + (uint32_t)(ubuf * TSU * 32 + prow) * 16;
            for (int s = s_begin; s < s_end; ++s) {
                const float x0 = xr[3 * s + 0];
                const float x1 = xr[3 * s + 1];
                const float x2 = xr[3 * s + 2];
                float u[NH];
#pragma unroll
                for (int j = 0; j < NH; j++) {
                    float v = fmaf(x0, wih[j][0], c[j]);
                    v = fmaf(x1, wih[j][1], v);
                    u[j] = fmaf(x2, wih[j][2], v);
                }
                const uint32_t p01 = h2u(__floats2half2_rn(u[0], u[1]));
                const uint32_t p23 = h2u(__floats2half2_rn(u[2], u[3]));
                const uint32_t p4x = h2u(__floats2half2_rn(u[4], 0.0f));
                asm volatile("st.shared.v4.u32 [%0], {%1, %2, %3, %4};"
                             :: "r"(ub + (uint32_t)s * (32 * 16)),
                                "r"(p01), "r"(p23), "r"(p4x), "r"(0u)
                             : "memory");
            }
        };

        // Prologue: stage x0..x2 (3 groups in flight); compute + publish u0.
        issue_x(0, 0);
        issue_x(1, 1);
        issue_x(2, 2);
        cp_wait1();          // <=1 pending -> x0, x1 landed
        producer_bar();      // all producers' x0 visible
        compute_u(0, 0);
        bar_arrive128(2);    // ready0: u0 published

        for (int t = 0; t + 1 < NTU; ++t) {
            const int nt   = t + 1;          // tile being produced
            const int npar = nt & 1;

            cp_wait1();          // x[t+1] landed (issued 2 iterations ago)
            producer_bar();      // x[t+1] visible; everyone done reading x[t]
            if (nt >= 2)
                bar_sync128(4 + npar);       // wait "free": u-buffer reusable
            compute_u(nt % XB, npar);
            const int ix = (t + 3 < NTU) ? (t + 3) : (NTU - 1);
            issue_x(ix, t % XB);             // reuse buffer x[t] occupied
            bar_arrive128(2 + npar);         // ready: u[t+1] published
        }
    }
}

extern "C" void kernel_launch(void* const* d_in, const int* in_sizes, int n_in,
                              void* d_out, int out_size)
{
    const float* state = (const float*)d_in[0];
    const float* W_ih  = (const float*)d_in[1];
    const float* W_hh  = (const float*)d_in[2];
    const float* b_ih  = (const float*)d_in[3];
    const float* b_hh  = (const float*)d_in[4];
    const float* W_out = (const float*)d_in[5];
    const float* b_out = (const float*)d_in[6];
    float* out = (float*)d_out;

    cudaFuncSetAttribute(rnn_relu_kernel,
                         cudaFuncAttributeMaxDynamicSharedMemorySize,
                         SMEM_TOTAL);

    const int B = in_sizes[0] / (TT * NIN3);  // 4096
    const int blocks = B / 32;                // 128
    rnn_relu_kernel<<<blocks, 128, SMEM_TOTAL>>>(state, W_ih, W_hh, b_ih, b_hh,
                                                 W_out, b_out, out, B);
}